// round 5
// baseline (speedup 1.0000x reference)
#include <cuda_runtime.h>
#include <cstdint>

__device__ float g_lig_proj[512 * 512];
__device__ float g_rec_proj[512 * 512];

#define D 512
#define BM 64
#define BN 64
#define BK 32
#define NKT (D / BK)
#define JBLK 64
#define IBLK 2

__device__ __forceinline__ uint32_t f2tf32(float x) {
    uint32_t r;
    asm("cvt.rna.tf32.f32 %0, %1;" : "=r"(r) : "f"(x));
    return r;
}

__device__ __forceinline__ void mma_tf32(float* d, const uint32_t* a, const uint32_t* b) {
    asm volatile(
        "mma.sync.aligned.m16n8k8.row.col.f32.tf32.tf32.f32 "
        "{%0,%1,%2,%3}, {%4,%5,%6,%7}, {%8,%9}, {%0,%1,%2,%3};"
        : "+f"(d[0]), "+f"(d[1]), "+f"(d[2]), "+f"(d[3])
        : "r"(a[0]), "r"(a[1]), "r"(a[2]), "r"(a[3]), "r"(b[0]), "r"(b[1]));
}

// C[i,o] = sum_k A[i,k] * W[o, w_off + k] (+ bias for receptor).
// tf32 tensor-core GEMM, hi/lo compensation (3 MMAs per logical MMA).
// hi/lo conversion done ONCE in the smem scatter phase, not in the MMA loop.
__global__ __launch_bounds__(256) void proj_gemm_kernel(
    const float* __restrict__ lig,
    const float* __restrict__ rec,
    const float* __restrict__ W,
    const float* __restrict__ bias)
{
    __shared__ uint32_t SaHi[BM * BK];   // fragment-ordered tf32 hi
    __shared__ uint32_t SaLo[BM * BK];
    __shared__ uint32_t SbHi[BN * BK];
    __shared__ uint32_t SbLo[BN * BK];

    const int z = blockIdx.z;
    const float* A = (z == 0) ? lig : rec;
    float* C = (z == 0) ? g_lig_proj : g_rec_proj;
    const int w_off_f4 = (z == 0) ? 0 : (D / 4);

    const int tid = threadIdx.x;
    const int lane = tid & 31;
    const int wid = tid >> 5;
    const int mwarp = wid >> 2;     // 0..1
    const int nwarp = wid & 3;      // 0..3
    const int i0 = blockIdx.y * BM;
    const int o0 = blockIdx.x * BN;

    const int lr0 = tid >> 3;       // 0..31
    const int lc  = tid & 7;        // float4 col 0..7
    const float4* A4 = reinterpret_cast<const float4*>(A);
    const float4* W4 = reinterpret_cast<const float4*>(W);

    float acc[2][2][4] = {};

    auto scatA = [&](int r, float4 v) {
        #pragma unroll
        for (int q = 0; q < 4; q++) {
            float val = (q == 0) ? v.x : (q == 1) ? v.y : (q == 2) ? v.z : v.w;
            int kl = lc * 4 + q;
            int mtile = r >> 4, ktile = kl >> 3;
            int rr = r & 15, cc = kl & 7;
            int ln = ((rr & 7) << 2) | (cc & 3);
            int idx = ((cc & 4) >> 1) | ((rr & 8) >> 3);
            int off = ((mtile * 4 + ktile) * 32 + ln) * 4 + idx;
            uint32_t hi = f2tf32(val);
            SaHi[off] = hi;
            SaLo[off] = f2tf32(val - __uint_as_float(hi));
        }
    };
    auto scatB = [&](int r, float4 v) {
        #pragma unroll
        for (int q = 0; q < 4; q++) {
            float val = (q == 0) ? v.x : (q == 1) ? v.y : (q == 2) ? v.z : v.w;
            int kl = lc * 4 + q;
            int ntile = r >> 3, ktile = kl >> 3;
            int n = r & 7, cc = kl & 7;
            int ln = (n << 2) | (cc & 3);
            int idx = (cc & 4) >> 2;
            int off = ((ntile * 4 + ktile) * 32 + ln) * 2 + idx;
            uint32_t hi = f2tf32(val);
            SbHi[off] = hi;
            SbLo[off] = f2tf32(val - __uint_as_float(hi));
        }
    };

    // Prologue: tile 0
    {
        float4 va0 = A4[(size_t)(i0 + lr0)      * (D / 4) + lc];
        float4 va1 = A4[(size_t)(i0 + lr0 + 32) * (D / 4) + lc];
        float4 vb0 = W4[(size_t)(o0 + lr0)      * (2 * D / 4) + w_off_f4 + lc];
        float4 vb1 = W4[(size_t)(o0 + lr0 + 32) * (2 * D / 4) + w_off_f4 + lc];
        scatA(lr0, va0); scatA(lr0 + 32, va1);
        scatB(lr0, vb0); scatB(lr0 + 32, vb1);
    }
    __syncthreads();

    for (int t = 0; t < NKT; t++) {
        float4 va0, va1, vb0, vb1;
        if (t + 1 < NKT) {
            const int kc4 = (t + 1) * (BK / 4);
            va0 = A4[(size_t)(i0 + lr0)      * (D / 4) + kc4 + lc];
            va1 = A4[(size_t)(i0 + lr0 + 32) * (D / 4) + kc4 + lc];
            vb0 = W4[(size_t)(o0 + lr0)      * (2 * D / 4) + w_off_f4 + kc4 + lc];
            vb1 = W4[(size_t)(o0 + lr0 + 32) * (2 * D / 4) + w_off_f4 + kc4 + lc];
        }

        #pragma unroll
        for (int k8 = 0; k8 < 4; k8++) {
            uint32_t ahi[2][4], alo[2][4], bhi[2][2], blo[2][2];
            #pragma unroll
            for (int mt = 0; mt < 2; mt++) {
                int base = (((mwarp * 2 + mt) * 4 + k8) * 32 + lane) * 4;
                *reinterpret_cast<uint4*>(ahi[mt]) = *reinterpret_cast<const uint4*>(&SaHi[base]);
                *reinterpret_cast<uint4*>(alo[mt]) = *reinterpret_cast<const uint4*>(&SaLo[base]);
            }
            #pragma unroll
            for (int nt = 0; nt < 2; nt++) {
                int base = (((nwarp * 2 + nt) * 4 + k8) * 32 + lane) * 2;
                *reinterpret_cast<uint2*>(bhi[nt]) = *reinterpret_cast<const uint2*>(&SbHi[base]);
                *reinterpret_cast<uint2*>(blo[nt]) = *reinterpret_cast<const uint2*>(&SbLo[base]);
            }
            #pragma unroll
            for (int mt = 0; mt < 2; mt++)
                #pragma unroll
                for (int nt = 0; nt < 2; nt++) {
                    mma_tf32(acc[mt][nt], ahi[mt], bhi[nt]);
                    mma_tf32(acc[mt][nt], alo[mt], bhi[nt]);
                    mma_tf32(acc[mt][nt], ahi[mt], blo[nt]);
                }
        }

        __syncthreads();
        if (t + 1 < NKT) {
            scatA(lr0, va0); scatA(lr0 + 32, va1);
            scatB(lr0, vb0); scatB(lr0 + 32, vb1);
            __syncthreads();
        }
    }

    #pragma unroll
    for (int mt = 0; mt < 2; mt++) {
        #pragma unroll
        for (int nt = 0; nt < 2; nt++) {
            int row = i0 + mwarp * 32 + mt * 16 + (lane >> 2);
            int col = o0 + nwarp * 16 + nt * 8 + 2 * (lane & 3);
            float bv0 = 0.f, bv1 = 0.f;
            if (z == 1) { bv0 = bias[col]; bv1 = bias[col + 1]; }
            float2 lo_pair = make_float2(acc[mt][nt][0] + bv0, acc[mt][nt][1] + bv1);
            float2 hi_pair = make_float2(acc[mt][nt][2] + bv0, acc[mt][nt][3] + bv1);
            *reinterpret_cast<float2*>(&C[(size_t)row * D + col]) = lo_pair;
            *reinterpret_cast<float2*>(&C[(size_t)(row + 8) * D + col]) = hi_pair;
        }
    }
}

// out[i, j, :] = lig_proj[i, :] + rec_proj[j, :]
// Block = (2 i's, 64 j's), 128 threads. Each rec load serves 2 output rows
// (halves L2 read traffic vs IBLK=1) while keeping 2048 blocks for occupancy.
__global__ __launch_bounds__(128) void pair_add_kernel(float4* __restrict__ out)
{
    const int c = threadIdx.x;            // float4 column 0..127
    const int i0 = blockIdx.y * IBLK;
    const int j0 = blockIdx.x * JBLK;

    const float4* lig = reinterpret_cast<const float4*>(g_lig_proj);
    const float4* rec = reinterpret_cast<const float4*>(g_rec_proj);

    const float4 a0 = lig[(i0 + 0) * 128 + c];
    const float4 a1 = lig[(i0 + 1) * 128 + c];

    const float4* rp = rec + (size_t)j0 * 128 + c;
    float4* op = out + ((size_t)i0 * D + j0) * 128 + c;

    for (int jj = 0; jj < JBLK; jj += 4) {
        float4 r[4];
        #pragma unroll
        for (int u = 0; u < 4; u++)
            r[u] = __ldg(rp + (size_t)(jj + u) * 128);
        #pragma unroll
        for (int u = 0; u < 4; u++) {
            float4 o0, o1;
            o0.x = a0.x + r[u].x; o0.y = a0.y + r[u].y;
            o0.z = a0.z + r[u].z; o0.w = a0.w + r[u].w;
            o1.x = a1.x + r[u].x; o1.y = a1.y + r[u].y;
            o1.z = a1.z + r[u].z; o1.w = a1.w + r[u].w;
            __stcs(op + (size_t)(jj + u) * 128, o0);
            __stcs(op + ((size_t)D + jj + u) * 128, o1);
        }
    }
}

extern "C" void kernel_launch(void* const* d_in, const int* in_sizes, int n_in,
                              void* d_out, int out_size)
{
    const float* lig = (const float*)d_in[0];   // (512, 512)
    const float* rec = (const float*)d_in[1];   // (512, 512)
    const float* W   = (const float*)d_in[2];   // (512, 1024)
    const float* b   = (const float*)d_in[3];   // (512,)
    float* out = (float*)d_out;                 // (512, 512, 512)

    dim3 ggrd(D / BN, D / BM, 2);   // 128 blocks
    proj_gemm_kernel<<<ggrd, 256>>>(lig, rec, W, b);

    dim3 agrd(D / JBLK, D / IBLK);  // 8 x 256 = 2048 blocks
    pair_add_kernel<<<agrd, 128>>>(reinterpret_cast<float4*>(out));
}

// round 6
// speedup vs baseline: 1.0040x; 1.0040x over previous
#include <cuda_runtime.h>
#include <cstdint>

__device__ float g_lig_proj[512 * 512];
__device__ float g_rec_proj[512 * 512];

#define D 512
#define BM 64
#define BN 64
#define BK 32
#define NKT (D / BK)
#define JBLK 16
#define IBLK 4

__device__ __forceinline__ uint32_t f2tf32(float x) {
    uint32_t r;
    asm("cvt.rna.tf32.f32 %0, %1;" : "=r"(r) : "f"(x));
    return r;
}

__device__ __forceinline__ void mma_tf32(float* d, const uint32_t* a, const uint32_t* b) {
    asm volatile(
        "mma.sync.aligned.m16n8k8.row.col.f32.tf32.tf32.f32 "
        "{%0,%1,%2,%3}, {%4,%5,%6,%7}, {%8,%9}, {%0,%1,%2,%3};"
        : "+f"(d[0]), "+f"(d[1]), "+f"(d[2]), "+f"(d[3])
        : "r"(a[0]), "r"(a[1]), "r"(a[2]), "r"(a[3]), "r"(b[0]), "r"(b[1]));
}

// C[i,o] = sum_k A[i,k] * W[o, w_off + k] (+ bias for receptor).
// tf32 tensor-core GEMM, hi/lo compensation (3 MMAs per logical MMA).
// hi/lo conversion done once in the smem scatter phase.
__global__ __launch_bounds__(256) void proj_gemm_kernel(
    const float* __restrict__ lig,
    const float* __restrict__ rec,
    const float* __restrict__ W,
    const float* __restrict__ bias)
{
    __shared__ uint32_t SaHi[BM * BK];
    __shared__ uint32_t SaLo[BM * BK];
    __shared__ uint32_t SbHi[BN * BK];
    __shared__ uint32_t SbLo[BN * BK];

    const int z = blockIdx.z;
    const float* A = (z == 0) ? lig : rec;
    float* C = (z == 0) ? g_lig_proj : g_rec_proj;
    const int w_off_f4 = (z == 0) ? 0 : (D / 4);

    const int tid = threadIdx.x;
    const int lane = tid & 31;
    const int wid = tid >> 5;
    const int mwarp = wid >> 2;     // 0..1
    const int nwarp = wid & 3;      // 0..3
    const int i0 = blockIdx.y * BM;
    const int o0 = blockIdx.x * BN;

    const int lr0 = tid >> 3;       // 0..31
    const int lc  = tid & 7;        // float4 col 0..7
    const float4* A4 = reinterpret_cast<const float4*>(A);
    const float4* W4 = reinterpret_cast<const float4*>(W);

    float acc[2][2][4] = {};

    auto scatA = [&](int r, float4 v) {
        #pragma unroll
        for (int q = 0; q < 4; q++) {
            float val = (q == 0) ? v.x : (q == 1) ? v.y : (q == 2) ? v.z : v.w;
            int kl = lc * 4 + q;
            int mtile = r >> 4, ktile = kl >> 3;
            int rr = r & 15, cc = kl & 7;
            int ln = ((rr & 7) << 2) | (cc & 3);
            int idx = ((cc & 4) >> 1) | ((rr & 8) >> 3);
            int off = ((mtile * 4 + ktile) * 32 + ln) * 4 + idx;
            uint32_t hi = f2tf32(val);
            SaHi[off] = hi;
            SaLo[off] = f2tf32(val - __uint_as_float(hi));
        }
    };
    auto scatB = [&](int r, float4 v) {
        #pragma unroll
        for (int q = 0; q < 4; q++) {
            float val = (q == 0) ? v.x : (q == 1) ? v.y : (q == 2) ? v.z : v.w;
            int kl = lc * 4 + q;
            int ntile = r >> 3, ktile = kl >> 3;
            int n = r & 7, cc = kl & 7;
            int ln = (n << 2) | (cc & 3);
            int idx = (cc & 4) >> 2;
            int off = ((ntile * 4 + ktile) * 32 + ln) * 2 + idx;
            uint32_t hi = f2tf32(val);
            SbHi[off] = hi;
            SbLo[off] = f2tf32(val - __uint_as_float(hi));
        }
    };

    {
        float4 va0 = A4[(size_t)(i0 + lr0)      * (D / 4) + lc];
        float4 va1 = A4[(size_t)(i0 + lr0 + 32) * (D / 4) + lc];
        float4 vb0 = W4[(size_t)(o0 + lr0)      * (2 * D / 4) + w_off_f4 + lc];
        float4 vb1 = W4[(size_t)(o0 + lr0 + 32) * (2 * D / 4) + w_off_f4 + lc];
        scatA(lr0, va0); scatA(lr0 + 32, va1);
        scatB(lr0, vb0); scatB(lr0 + 32, vb1);
    }
    __syncthreads();

    for (int t = 0; t < NKT; t++) {
        float4 va0, va1, vb0, vb1;
        if (t + 1 < NKT) {
            const int kc4 = (t + 1) * (BK / 4);
            va0 = A4[(size_t)(i0 + lr0)      * (D / 4) + kc4 + lc];
            va1 = A4[(size_t)(i0 + lr0 + 32) * (D / 4) + kc4 + lc];
            vb0 = W4[(size_t)(o0 + lr0)      * (2 * D / 4) + w_off_f4 + kc4 + lc];
            vb1 = W4[(size_t)(o0 + lr0 + 32) * (2 * D / 4) + w_off_f4 + kc4 + lc];
        }

        #pragma unroll
        for (int k8 = 0; k8 < 4; k8++) {
            uint32_t ahi[2][4], alo[2][4], bhi[2][2], blo[2][2];
            #pragma unroll
            for (int mt = 0; mt < 2; mt++) {
                int base = (((mwarp * 2 + mt) * 4 + k8) * 32 + lane) * 4;
                *reinterpret_cast<uint4*>(ahi[mt]) = *reinterpret_cast<const uint4*>(&SaHi[base]);
                *reinterpret_cast<uint4*>(alo[mt]) = *reinterpret_cast<const uint4*>(&SaLo[base]);
            }
            #pragma unroll
            for (int nt = 0; nt < 2; nt++) {
                int base = (((nwarp * 2 + nt) * 4 + k8) * 32 + lane) * 2;
                *reinterpret_cast<uint2*>(bhi[nt]) = *reinterpret_cast<const uint2*>(&SbHi[base]);
                *reinterpret_cast<uint2*>(blo[nt]) = *reinterpret_cast<const uint2*>(&SbLo[base]);
            }
            #pragma unroll
            for (int mt = 0; mt < 2; mt++)
                #pragma unroll
                for (int nt = 0; nt < 2; nt++) {
                    mma_tf32(acc[mt][nt], ahi[mt], bhi[nt]);
                    mma_tf32(acc[mt][nt], alo[mt], bhi[nt]);
                    mma_tf32(acc[mt][nt], ahi[mt], blo[nt]);
                }
        }

        __syncthreads();
        if (t + 1 < NKT) {
            scatA(lr0, va0); scatA(lr0 + 32, va1);
            scatB(lr0, vb0); scatB(lr0 + 32, vb1);
            __syncthreads();
        }
    }

    #pragma unroll
    for (int mt = 0; mt < 2; mt++) {
        #pragma unroll
        for (int nt = 0; nt < 2; nt++) {
            int row = i0 + mwarp * 32 + mt * 16 + (lane >> 2);
            int col = o0 + nwarp * 16 + nt * 8 + 2 * (lane & 3);
            float bv0 = 0.f, bv1 = 0.f;
            if (z == 1) { bv0 = bias[col]; bv1 = bias[col + 1]; }
            float2 lo_pair = make_float2(acc[mt][nt][0] + bv0, acc[mt][nt][1] + bv1);
            float2 hi_pair = make_float2(acc[mt][nt][2] + bv0, acc[mt][nt][3] + bv1);
            *reinterpret_cast<float2*>(&C[(size_t)row * D + col]) = lo_pair;
            *reinterpret_cast<float2*>(&C[(size_t)(row + 8) * D + col]) = hi_pair;
        }
    }
}

// out[i, j, :] = lig_proj[i, :] + rec_proj[j, :]
// Block = (4 i's, 16 j's), 128 threads, grid 32x128 = 4096 blocks.
// Same block count as the best round (occupancy ~80%) but each rec load now
// serves 4 output rows -> L2 read traffic down 4x, LTS path free for stores.
__global__ __launch_bounds__(128) void pair_add_kernel(float4* __restrict__ out)
{
    const int c = threadIdx.x;            // float4 column 0..127
    const int i0 = blockIdx.y * IBLK;
    const int j0 = blockIdx.x * JBLK;

    const float4* lig = reinterpret_cast<const float4*>(g_lig_proj);
    const float4* rec = reinterpret_cast<const float4*>(g_rec_proj);

    float4 a[IBLK];
    #pragma unroll
    for (int u = 0; u < IBLK; u++)
        a[u] = lig[(i0 + u) * 128 + c];

    const float4* rp = rec + (size_t)j0 * 128 + c;
    float4* op = out + ((size_t)i0 * D + j0) * 128 + c;

    for (int jj = 0; jj < JBLK; jj += 4) {
        float4 r[4];
        #pragma unroll
        for (int v = 0; v < 4; v++)
            r[v] = __ldg(rp + (size_t)(jj + v) * 128);
        #pragma unroll
        for (int v = 0; v < 4; v++) {
            #pragma unroll
            for (int u = 0; u < IBLK; u++) {
                float4 o;
                o.x = a[u].x + r[v].x;
                o.y = a[u].y + r[v].y;
                o.z = a[u].z + r[v].z;
                o.w = a[u].w + r[v].w;
                __stcs(op + ((size_t)u * D + jj + v) * 128, o);
            }
        }
    }
}

extern "C" void kernel_launch(void* const* d_in, const int* in_sizes, int n_in,
                              void* d_out, int out_size)
{
    const float* lig = (const float*)d_in[0];   // (512, 512)
    const float* rec = (const float*)d_in[1];   // (512, 512)
    const float* W   = (const float*)d_in[2];   // (512, 1024)
    const float* b   = (const float*)d_in[3];   // (512,)
    float* out = (float*)d_out;                 // (512, 512, 512)

    dim3 ggrd(D / BN, D / BM, 2);   // 128 blocks
    proj_gemm_kernel<<<ggrd, 256>>>(lig, rec, W, b);

    dim3 agrd(D / JBLK, D / IBLK);  // 32 x 128 = 4096 blocks
    pair_add_kernel<<<agrd, 128>>>(reinterpret_cast<float4*>(out));
}